// round 13
// baseline (speedup 1.0000x reference)
#include <cuda_runtime.h>
#include <math.h>

// ---------------- problem constants ----------------
#define BQ   8
#define LQ   128
#define TSEQ 384          // 3 * L tokens per batch
#define MTOK 3072         // BQ * TSEQ
#define DM   256          // d_model
#define DI   512          // d_inner
#define DS   16           // d_state
#define RK   16           // dt_rank
#define NL   4
#define NB   256          // persistent blocks (<= 296 resident at occ 2)
#define NT   256          // threads per block

// ---------------- scratch (device globals; no allocation allowed) ----------------
__device__ float g_u  [MTOK * DM];
__device__ float g_res[MTOK * DM];
__device__ float g_rs [MTOK];
__device__ float g_xz [MTOK * 2 * DI];
__device__ float g_xc [MTOK * DI];
__device__ float g_proj[MTOK * 48];
__device__ float g_y  [MTOK * DI];
__device__ unsigned g_bar;

__global__ void k_reset() { g_bar = 0u; }

// ---------------- grid barrier (monotonic counter; reset per launch) ----------
__device__ __forceinline__ void gbar(unsigned& tgt)
{
    __syncthreads();
    if (threadIdx.x == 0) {
        tgt += NB;
        __threadfence();
        atomicAdd(&g_bar, 1u);
        while (*((volatile unsigned*)&g_bar) < tgt) { }
        __threadfence();
    }
    __syncthreads();
}

// ---------------- phase: embeddings + interleave -> u ----------------
__device__ __forceinline__ void embed_phase(
    const float* __restrict__ states, const float* __restrict__ actions,
    const float* __restrict__ goal, const int* __restrict__ timesteps,
    const float* __restrict__ te_W,
    const float* __restrict__ se_W, const float* __restrict__ se_b,
    const float* __restrict__ ge_W, const float* __restrict__ ge_b,
    const float* __restrict__ ae_W, const float* __restrict__ ae_b)
{
    int e = threadIdx.x;
    for (int m = blockIdx.x; m < MTOK; m += NB) {
        int b = m / TSEQ, t = m % TSEQ;
        int slot = t % 3, l = t / 3;
        const float *inp, *Wm, *bi; int dim;
        if (slot == 0)      { inp = goal;    Wm = ge_W; bi = ge_b; dim = 6; }
        else if (slot == 1) { inp = states;  Wm = se_W; bi = se_b; dim = 6; }
        else                { inp = actions; Wm = ae_W; bi = ae_b; dim = 3; }
        float v = bi[e];
        const float* ip = inp + (size_t)(b * LQ + l) * dim;
        #pragma unroll 6
        for (int i = 0; i < dim; i++) v += ip[i] * Wm[i * DM + e];
        v += te_W[(size_t)timesteps[b * LQ + l] * DM + e];
        g_u[(size_t)m * DM + e] = v;
    }
}

// ---------------- phase: per-row rmsnorm scales ----------------
__device__ __forceinline__ void rowscale_phase()
{
    int lane = threadIdx.x & 31;
    for (int row = blockIdx.x * 8 + (threadIdx.x >> 5); row < MTOK; row += NB * 8) {
        const float4* p = (const float4*)(g_res + (size_t)row * DM);
        float s = 0.f;
        #pragma unroll
        for (int i = lane; i < DM / 4; i += 32) {
            float4 v = p[i];
            s += v.x * v.x + v.y * v.y + v.z * v.z + v.w * v.w;
        }
        #pragma unroll
        for (int o = 16; o > 0; o >>= 1) s += __shfl_down_sync(0xffffffffu, s, o);
        if (lane == 0) g_rs[row] = rsqrtf(s * (1.f / DM) + 1e-5f);
    }
}

// ---------------- phase: 128x64 prefetched SGEMM (proven inner loop) ----------
// EPI 0: C = acc (+bias);  EPI 2: atomicAdd(C, acc) for split-K.
// NORM: A-load scaled by g_rs[row]*nw[k].
template<int EPI, bool NORM>
__device__ __forceinline__ void gemm_phase(
    const float* __restrict__ A, int lda,
    const float* __restrict__ W, int N, int K, int nks,
    const float* __restrict__ bias, const float* __restrict__ nw,
    float* __restrict__ C, int ldc, float* __restrict__ sm)
{
    float* As = sm;          // [16][128]
    float* Ws = sm + 2048;   // [16][68]
    int tid = threadIdx.x;
    int ntx = N >> 6, nty = MTOK >> 7;
    int tiles = ntx * nty * nks;
    int tx = tid & 15, ty = tid >> 4;
    int arow = tid >> 2, acol = (tid & 3) * 4;
    int wk = tid >> 4, wn = (tid & 15) * 4;

    for (int vt = blockIdx.x; vt < tiles; vt += NB) {
        int bx = vt % ntx;
        int rem = vt / ntx;
        int by = rem % nty, bz = rem / nty;
        int bm = by * 128, bn = bx * 64, kb = bz * K;

        float s0 = 1.f, s1 = 1.f;
        if (NORM) { s0 = g_rs[bm + arow]; s1 = g_rs[bm + arow + 64]; }

        const float* Ap0 = A + (size_t)(bm + arow) * lda + kb + acol;
        const float* Ap1 = Ap0 + (size_t)64 * lda;
        float4 pa0 = *(const float4*)(Ap0);
        float4 pa1 = *(const float4*)(Ap1);
        float4 pw  = *(const float4*)(W + (size_t)(kb + wk) * N + bn + wn);

        float acc[8][4] = {};

        for (int k0 = 0; k0 < K; k0 += 16) {
            __syncthreads();
            if (NORM) {
                float n0 = nw[k0 + acol + 0], n1 = nw[k0 + acol + 1];
                float n2 = nw[k0 + acol + 2], n3 = nw[k0 + acol + 3];
                As[(acol + 0) * 128 + arow] = pa0.x * s0 * n0;
                As[(acol + 1) * 128 + arow] = pa0.y * s0 * n1;
                As[(acol + 2) * 128 + arow] = pa0.z * s0 * n2;
                As[(acol + 3) * 128 + arow] = pa0.w * s0 * n3;
                As[(acol + 0) * 128 + arow + 64] = pa1.x * s1 * n0;
                As[(acol + 1) * 128 + arow + 64] = pa1.y * s1 * n1;
                As[(acol + 2) * 128 + arow + 64] = pa1.z * s1 * n2;
                As[(acol + 3) * 128 + arow + 64] = pa1.w * s1 * n3;
            } else {
                As[(acol + 0) * 128 + arow] = pa0.x;
                As[(acol + 1) * 128 + arow] = pa0.y;
                As[(acol + 2) * 128 + arow] = pa0.z;
                As[(acol + 3) * 128 + arow] = pa0.w;
                As[(acol + 0) * 128 + arow + 64] = pa1.x;
                As[(acol + 1) * 128 + arow + 64] = pa1.y;
                As[(acol + 2) * 128 + arow + 64] = pa1.z;
                As[(acol + 3) * 128 + arow + 64] = pa1.w;
            }
            *(float4*)&Ws[wk * 68 + wn] = pw;
            __syncthreads();

            if (k0 + 16 < K) {
                pa0 = *(const float4*)(Ap0 + k0 + 16);
                pa1 = *(const float4*)(Ap1 + k0 + 16);
                pw  = *(const float4*)(W + (size_t)(kb + k0 + 16 + wk) * N + bn + wn);
            }

            #pragma unroll
            for (int k = 0; k < 16; k++) {
                float4 a0 = *(const float4*)&As[k * 128 + ty * 8];
                float4 a1 = *(const float4*)&As[k * 128 + ty * 8 + 4];
                float4 w0 = *(const float4*)&Ws[k * 68 + tx * 4];
                float a[8] = {a0.x, a0.y, a0.z, a0.w, a1.x, a1.y, a1.z, a1.w};
                float w[4] = {w0.x, w0.y, w0.z, w0.w};
                #pragma unroll
                for (int i = 0; i < 8; i++)
                    #pragma unroll
                    for (int j = 0; j < 4; j++) acc[i][j] += a[i] * w[j];
            }
        }
        __syncthreads();   // protect smem before next tile's writes

        #pragma unroll
        for (int i = 0; i < 8; i++) {
            int row = bm + ty * 8 + i;
            #pragma unroll
            for (int j = 0; j < 4; j++) {
                int col = bn + tx * 4 + j;
                float v = acc[i][j];
                if (EPI == 0) {
                    if (bias) v += bias[col];
                    C[(size_t)row * ldc + col] = v;
                } else {
                    atomicAdd(&C[(size_t)row * ldc + col], v);
                }
            }
        }
    }
}

// ---------------- phase: conv (k=4) + silu, 4 tokens/thread; zero proj --------
__device__ __forceinline__ void conv_phase(const float* __restrict__ cw,
                                           const float* __restrict__ cb)
{
    int base = blockIdx.x * NT + threadIdx.x;
    for (int i = base; i < MTOK * 48; i += NB * NT) g_proj[i] = 0.f;

    for (int idx = base; idx < (MTOK / 4) * (DI / 4); idx += NB * NT) {
        int mg = idx / (DI / 4), dv = idx % (DI / 4);
        int d = dv * 4;
        int b = mg / (TSEQ / 4), tg = mg % (TSEQ / 4);
        int t0 = tg * 4;

        float4 win[7];
        #pragma unroll
        for (int j = 0; j < 7; j++) {
            int tt = t0 - 3 + j;
            win[j] = (tt >= 0)
                ? *(const float4*)(g_xz + (size_t)(b * TSEQ + tt) * (2 * DI) + d)
                : make_float4(0.f, 0.f, 0.f, 0.f);
        }
        float4 cw0 = *(const float4*)(cw + (d + 0) * 4);
        float4 cw1 = *(const float4*)(cw + (d + 1) * 4);
        float4 cw2 = *(const float4*)(cw + (d + 2) * 4);
        float4 cw3 = *(const float4*)(cw + (d + 3) * 4);
        float4 cb4 = *(const float4*)(cb + d);
        float cwk[4][4] = {{cw0.x, cw0.y, cw0.z, cw0.w},
                           {cw1.x, cw1.y, cw1.z, cw1.w},
                           {cw2.x, cw2.y, cw2.z, cw2.w},
                           {cw3.x, cw3.y, cw3.z, cw3.w}};
        #pragma unroll
        for (int j2 = 0; j2 < 4; j2++) {
            float4 acc = cb4;
            #pragma unroll
            for (int k = 0; k < 4; k++) {
                float4 v = win[j2 + k];
                acc.x += cwk[0][k] * v.x;
                acc.y += cwk[1][k] * v.y;
                acc.z += cwk[2][k] * v.z;
                acc.w += cwk[3][k] * v.w;
            }
            acc.x = acc.x / (1.f + __expf(-acc.x));
            acc.y = acc.y / (1.f + __expf(-acc.y));
            acc.z = acc.z / (1.f + __expf(-acc.z));
            acc.w = acc.w / (1.f + __expf(-acc.w));
            *(float4*)(g_xc + (size_t)(b * TSEQ + t0 + j2) * DI + d) = acc;
        }
    }
}

// ---------------- phase: xproj 64x64 split-K x4, atomic epilogue --------------
__device__ __forceinline__ void xproj_phase(const float* __restrict__ W,
                                            float* __restrict__ sm)
{
    float* As = sm;          // [16][64]
    float* Ws = sm + 1024;   // [16][68]
    int tid = threadIdx.x;
    int tx = tid & 15, ty = tid >> 4;
    int arow = tid >> 2, acol = (tid & 3) << 2;
    int wn = tx * 4;
    bool wok = wn < 48;
    const int Ks = DI / 4;

    for (int vt = blockIdx.x; vt < 48 * 4; vt += NB) {
        int by = vt % 48, bz = vt / 48;
        int bm = by * 64, kb = bz * Ks;

        const float* Arow = g_xc + (size_t)(bm + arow) * DI + acol;
        float4 pa = *(const float4*)(Arow + kb);
        float4 pw = make_float4(0.f, 0.f, 0.f, 0.f);
        if (wok) pw = *(const float4*)(W + (size_t)(kb + ty) * 48 + wn);

        float acc[4][4] = {};

        for (int k0 = kb; k0 < kb + Ks; k0 += 16) {
            __syncthreads();
            As[(acol + 0) * 64 + arow] = pa.x;
            As[(acol + 1) * 64 + arow] = pa.y;
            As[(acol + 2) * 64 + arow] = pa.z;
            As[(acol + 3) * 64 + arow] = pa.w;
            *(float4*)&Ws[ty * 68 + wn] = pw;
            __syncthreads();

            if (k0 + 16 < kb + Ks) {
                pa = *(const float4*)(Arow + k0 + 16);
                if (wok) pw = *(const float4*)(W + (size_t)(k0 + 16 + ty) * 48 + wn);
            }

            #pragma unroll
            for (int k = 0; k < 16; k++) {
                float4 a0 = *(const float4*)&As[k * 64 + ty * 4];
                float4 w0 = *(const float4*)&Ws[k * 68 + tx * 4];
                float a[4] = {a0.x, a0.y, a0.z, a0.w};
                float w[4] = {w0.x, w0.y, w0.z, w0.w};
                #pragma unroll
                for (int i = 0; i < 4; i++)
                    #pragma unroll
                    for (int j = 0; j < 4; j++) acc[i][j] += a[i] * w[j];
            }
        }
        __syncthreads();

        #pragma unroll
        for (int i = 0; i < 4; i++) {
            int row = bm + ty * 4 + i;
            #pragma unroll
            for (int j = 0; j < 4; j++) {
                int col = tx * 4 + j;
                if (col < 48) atomicAdd(&g_proj[(size_t)row * 48 + col], acc[i][j]);
            }
        }
    }
}

// ---------------- phase: selective scan (64 active lanes per active block) ----
__device__ __forceinline__ void scan_phase(
    const float* __restrict__ A_log, const float* __restrict__ Dp,
    const float* __restrict__ dtW, const float* __restrict__ dtb,
    float* __restrict__ sm)
{
    int vb = blockIdx.x;
    if (vb >= 64) return;                 // block-local; no cross-block syncs inside
    float* sp = sm;                        // [8][48]
    int tid = threadIdx.x;
    int b = vb >> 3;
    bool act = tid < 64;
    int d = ((vb & 7) << 6) + (tid & 63);

    float h[16];
    #pragma unroll
    for (int n = 0; n < 16; n++) h[n] = 0.f;

    float A0 = 0.f, bd = 0.f, Dd = 0.f;
    float W16[16];
    bool lin = true;
    if (act) {
        A0 = -__expf(A_log[d * DS]);
        #pragma unroll
        for (int n = 0; n < 16; n++) {
            float An = -__expf(A_log[d * DS + n]);
            lin = lin && (fabsf(An - (float)(n + 1) * A0) <= 1e-4f * fabsf(An));
        }
        #pragma unroll
        for (int r = 0; r < 16; r++) W16[r] = dtW[r * DI + d];
        bd = dtb[d]; Dd = Dp[d];
    }

    for (int t0 = 0; t0 < TSEQ; t0 += 8) {
        __syncthreads();
        for (int i = tid; i < 384; i += NT)
            sp[i] = g_proj[(size_t)(b * TSEQ + t0 + i / 48) * 48 + (i % 48)];
        float xc8[8], z8[8];
        if (act) {
            #pragma unroll
            for (int i = 0; i < 8; i++)
                xc8[i] = g_xc[(size_t)(b * TSEQ + t0 + i) * DI + d];
            #pragma unroll
            for (int i = 0; i < 8; i++)
                z8[i] = g_xz[(size_t)(b * TSEQ + t0 + i) * (2 * DI) + DI + d];
        }
        __syncthreads();

        if (act) {
            float dtx8[8], p8[8], gz8[8], xD8[8];
            #pragma unroll
            for (int tt = 0; tt < 8; tt++) {
                float dtr = bd;
                #pragma unroll
                for (int r = 0; r < 16; r++) dtr += sp[tt * 48 + r] * W16[r];
                float dt = (dtr > 15.f) ? dtr : log1pf(__expf(dtr));
                float x = xc8[tt];
                dtx8[tt] = dt * x;
                p8[tt] = lin ? __expf(dt * A0) : dt;
                float z = z8[tt];
                gz8[tt] = z / (1.f + __expf(-z));
                xD8[tt] = x * Dd;
            }

            #pragma unroll
            for (int tt = 0; tt < 8; tt++) {
                float dA[16];
                if (lin) {
                    float p = p8[tt], p2 = p * p;
                    float c1 = p, c2 = p2;
                    dA[0] = c1; dA[1] = c2;
                    #pragma unroll
                    for (int j = 2; j < 16; j += 2) {
                        c1 *= p2; c2 *= p2;
                        dA[j] = c1; dA[j + 1] = c2;
                    }
                } else {
                    // never taken for this model; recompute A from global (slow path)
                    #pragma unroll
                    for (int n = 0; n < 16; n++)
                        dA[n] = __expf(p8[tt] * (-__expf(A_log[d * DS + n])));
                }
                float dtx = dtx8[tt];
                float y0 = 0.f, y1 = 0.f, y2 = 0.f, y3 = 0.f;
                #pragma unroll
                for (int n = 0; n < 16; n += 4) {
                    h[n + 0] = dA[n + 0] * h[n + 0] + dtx * sp[tt * 48 + 16 + n + 0];
                    h[n + 1] = dA[n + 1] * h[n + 1] + dtx * sp[tt * 48 + 16 + n + 1];
                    h[n + 2] = dA[n + 2] * h[n + 2] + dtx * sp[tt * 48 + 16 + n + 2];
                    h[n + 3] = dA[n + 3] * h[n + 3] + dtx * sp[tt * 48 + 16 + n + 3];
                    y0 += h[n + 0] * sp[tt * 48 + 32 + n + 0];
                    y1 += h[n + 1] * sp[tt * 48 + 32 + n + 1];
                    y2 += h[n + 2] * sp[tt * 48 + 32 + n + 2];
                    y3 += h[n + 3] * sp[tt * 48 + 32 + n + 3];
                }
                float y = (y0 + y1) + (y2 + y3);
                g_y[(size_t)(b * TSEQ + t0 + tt) * DI + d] = (y + xD8[tt]) * gz8[tt];
            }
        }
    }
}

// ---------------- phase: heads with fused final rmsnorm ----------------
__device__ __forceinline__ void heads_phase(
    const float* __restrict__ fnw,
    const float* __restrict__ ps_W, const float* __restrict__ ps_b,
    const float* __restrict__ pa_W, const float* __restrict__ pa_b,
    float* __restrict__ out)
{
    for (int idx = blockIdx.x * NT + threadIdx.x; idx < 9216; idx += NB * NT) {
        if (idx < 6144) {
            int j = idx % 6; int l = (idx / 6) % LQ; int b = idx / (6 * LQ);
            int m = b * TSEQ + l * 3 + 2;
            float acc = 0.f;
            const float* f = g_res + (size_t)m * DM;
            #pragma unroll 8
            for (int e = 0; e < DM; e++) acc += f[e] * fnw[e] * ps_W[e * 6 + j];
            out[idx] = acc * g_rs[m] + ps_b[j];
        } else {
            int k = idx - 6144;
            int j = k % 3; int l = (k / 3) % LQ; int b = k / (3 * LQ);
            int m = b * TSEQ + l * 3 + 1;
            float acc = 0.f;
            const float* f = g_res + (size_t)m * DM;
            #pragma unroll 8
            for (int e = 0; e < DM; e++) acc += f[e] * fnw[e] * pa_W[e * 3 + j];
            out[idx] = tanhf(acc * g_rs[m] + pa_b[j]);
        }
    }
}

// ---------------- THE megakernel ----------------
__global__ __launch_bounds__(NT, 2)
void k_mega(const float* states, const float* actions, const float* goal,
            const int* timesteps, const float* te_W,
            const float* se_W, const float* se_b,
            const float* ge_W, const float* ge_b,
            const float* ae_W, const float* ae_b,
            const float* bb_in_W, const float* bb_in_b,
            const float* norm_w, const float* in_proj_W,
            const float* conv_w, const float* conv_b,
            const float* xproj_W, const float* dt_W, const float* dt_b,
            const float* A_log, const float* Dp, const float* out_W,
            const float* fnorm_w,
            const float* ps_W, const float* ps_b,
            const float* pa_W, const float* pa_b,
            float* out)
{
    __shared__ float sm[2048 + 16 * 68];   // 12.6 KB pool shared by all phases
    unsigned tgt = 0;

    embed_phase(states, actions, goal, timesteps, te_W,
                se_W, se_b, ge_W, ge_b, ae_W, ae_b);
    gbar(tgt);

    gemm_phase<0, false>(g_u, DM, bb_in_W, DM, DM, 1, bb_in_b, nullptr,
                         g_res, DM, sm);
    gbar(tgt);

    for (int i = 0; i < NL; i++) {
        const float* inW  = in_proj_W + (size_t)i * DM * 2 * DI;
        const float* cw   = conv_w    + (size_t)i * DI * 4;
        const float* cb   = conv_b    + (size_t)i * DI;
        const float* xpW  = xproj_W   + (size_t)i * DI * 48;
        const float* dtW  = dt_W      + (size_t)i * RK * DI;
        const float* dtb  = dt_b      + (size_t)i * DI;
        const float* Al   = A_log     + (size_t)i * DI * DS;
        const float* Dpi  = Dp        + (size_t)i * DI;
        const float* oW   = out_W     + (size_t)i * DI * DM;
        const float* nw   = norm_w    + (size_t)i * DM;

        rowscale_phase();
        gbar(tgt);

        gemm_phase<0, true>(g_res, DM, inW, 2 * DI, DM, 1, nullptr, nw,
                            g_xz, 2 * DI, sm);
        gbar(tgt);

        conv_phase(cw, cb);
        gbar(tgt);

        xproj_phase(xpW, sm);
        gbar(tgt);

        scan_phase(Al, Dpi, dtW, dtb, sm);
        gbar(tgt);

        gemm_phase<2, false>(g_y, DI, oW, DM, DI / 2, 2, nullptr, nullptr,
                             g_res, DM, sm);
        gbar(tgt);
    }

    rowscale_phase();
    gbar(tgt);

    heads_phase(fnorm_w, ps_W, ps_b, pa_W, pa_b, out);
}

// ---------------- launch ----------------
extern "C" void kernel_launch(void* const* d_in, const int* in_sizes, int n_in,
                              void* d_out, int out_size)
{
    const float* states    = (const float*)d_in[0];
    const float* actions   = (const float*)d_in[1];
    const float* goal      = (const float*)d_in[2];
    const int*   timesteps = (const int*)  d_in[3];
    const float* te_W      = (const float*)d_in[4];
    const float* se_W      = (const float*)d_in[5];
    const float* se_b      = (const float*)d_in[6];
    const float* ge_W      = (const float*)d_in[7];
    const float* ge_b      = (const float*)d_in[8];
    const float* ae_W      = (const float*)d_in[9];
    const float* ae_b      = (const float*)d_in[10];
    const float* bb_in_W   = (const float*)d_in[11];
    const float* bb_in_b   = (const float*)d_in[12];
    const float* norm_w    = (const float*)d_in[13];
    const float* in_proj_W = (const float*)d_in[14];
    const float* conv_w    = (const float*)d_in[15];
    const float* conv_b    = (const float*)d_in[16];
    const float* xproj_W   = (const float*)d_in[17];
    const float* dt_W      = (const float*)d_in[18];
    const float* dt_b      = (const float*)d_in[19];
    const float* A_log     = (const float*)d_in[20];
    const float* Dp        = (const float*)d_in[21];
    const float* out_W     = (const float*)d_in[22];
    const float* fnorm_w   = (const float*)d_in[23];
    const float* ps_W      = (const float*)d_in[24];
    const float* ps_b      = (const float*)d_in[25];
    const float* pa_W      = (const float*)d_in[26];
    const float* pa_b      = (const float*)d_in[27];
    float* out = (float*)d_out;

    k_reset<<<1, 1>>>();
    k_mega<<<NB, NT>>>(states, actions, goal, timesteps, te_W,
                       se_W, se_b, ge_W, ge_b, ae_W, ae_b,
                       bb_in_W, bb_in_b, norm_w, in_proj_W,
                       conv_w, conv_b, xproj_W, dt_W, dt_b,
                       A_log, Dp, out_W, fnorm_w,
                       ps_W, ps_b, pa_W, pa_b, out);
}